// round 9
// baseline (speedup 1.0000x reference)
#include <cuda_runtime.h>
#include <stdint.h>

// out[e,f] = (node_src[src[e],f] + off_src[e,f]) * (node_tgt[tgt[e],f] + off_tgt[e,f])
// F = 256 floats, E = 300000, N = 50000, edge_ids int32. HBM-bound.
//
// Feature-phase slicing, 2 phases x 128 columns (phase = blockIdx.y):
//  - per-phase gathered node working set = 2 x 25.6 MB = 51.2 MB -> L2-resident
//  - streams touched in 512 B fragments per 1 KB row (vs 256 B at 4 phases):
//    keeps DRAM burst locality high
//  - streams + output evict-first (.cs), zero reuse
// Each thread handles 8 floats (2 float4 per operand); 16 threads per edge
// per phase; 16 edges per 256-thread block.

#define NPHASE 2
#define GP     16  // 8-float groups per phase per row (16*8 = 128 cols)

__global__ __launch_bounds__(256) void node_to_edge_phased_kernel(
    const float4* __restrict__ node_src,   // [N, 64] as float4
    const float4* __restrict__ node_tgt,
    const int* __restrict__ edge_src_ids,  // [E]
    const int* __restrict__ edge_tgt_ids,  // [E]
    const float4* __restrict__ off_src,    // [E, 64]
    const float4* __restrict__ off_tgt,
    float4* __restrict__ out,              // [E, 64]
    unsigned E)
{
    unsigned tid   = blockIdx.x * blockDim.x + threadIdx.x;
    unsigned e     = tid >> 4;            // 16 threads per edge
    unsigned g     = tid & 15;            // group within phase
    if (e >= E) return;
    unsigned grp = blockIdx.y * GP + g;   // 8-float group within row, 0..31

    long long s = (long long)edge_src_ids[e];
    long long t = (long long)edge_tgt_ids[e];

    long long q  = (long long)e * 64 + grp * 2;   // float4 index in edge row
    long long sq = s * 64 + grp * 2;
    long long tq = t * 64 + grp * 2;

    // Gathered node slices (51.2 MB/phase working set): default caching.
    float4 a0 = __ldg(&node_src[sq]);
    float4 a1 = __ldg(&node_src[sq + 1]);
    float4 c0 = __ldg(&node_tgt[tq]);
    float4 c1 = __ldg(&node_tgt[tq + 1]);

    // Single-use streams: evict-first.
    float4 b0 = __ldcs(&off_src[q]);
    float4 b1 = __ldcs(&off_src[q + 1]);
    float4 d0 = __ldcs(&off_tgt[q]);
    float4 d1 = __ldcs(&off_tgt[q + 1]);

    float4 r0, r1;
    r0.x = (a0.x + b0.x) * (c0.x + d0.x);
    r0.y = (a0.y + b0.y) * (c0.y + d0.y);
    r0.z = (a0.z + b0.z) * (c0.z + d0.z);
    r0.w = (a0.w + b0.w) * (c0.w + d0.w);
    r1.x = (a1.x + b1.x) * (c1.x + d1.x);
    r1.y = (a1.y + b1.y) * (c1.y + d1.y);
    r1.z = (a1.z + b1.z) * (c1.z + d1.z);
    r1.w = (a1.w + b1.w) * (c1.w + d1.w);

    __stcs(&out[q], r0);
    __stcs(&out[q + 1], r1);
}

extern "C" void kernel_launch(void* const* d_in, const int* in_sizes, int n_in,
                              void* d_out, int out_size) {
    // 0: node_src_feats [N,256] f32   1: node_tgt_feats [N,256] f32
    // 2: edge_ids [2,E] int32         3: off_edge_src [E,256] f32
    // 4: off_edge_tgt [E,256] f32
    const float4* node_src = (const float4*)d_in[0];
    const float4* node_tgt = (const float4*)d_in[1];
    const int*    edge_ids = (const int*)d_in[2];
    const float4* off_src  = (const float4*)d_in[3];
    const float4* off_tgt  = (const float4*)d_in[4];
    float4*       out      = (float4*)d_out;

    unsigned E = (unsigned)(in_sizes[2] / 2);
    const int* src_ids = edge_ids;
    const int* tgt_ids = edge_ids + E;

    // 16 edges per block per phase
    unsigned blocks_per_phase = (E + 15) / 16;
    dim3 grid(blocks_per_phase, NPHASE, 1);

    node_to_edge_phased_kernel<<<grid, 256>>>(
        node_src, node_tgt, src_ids, tgt_ids, off_src, off_tgt, out, E);
}